// round 1
// baseline (speedup 1.0000x reference)
#include <cuda_runtime.h>
#include <math.h>

// ---------------- problem constants ----------------
#define BATCH 4
#define HW    112
#define NTOK  12544            // 112*112
#define CDIM  256
#define GH    4
#define HD    32
#define GD    128
#define LD    128
#define HID   1024
#define WSZ   7
#define NG    16                // 112/7
#define MPOOL 256               // 16*16 pooled tokens
#define ROWS  (BATCH*NTOK)      // 50176
#define ATT_SCALE 0.17677669529663687f  // 32^-0.5

// ---------------- scratch (device globals; no allocation) ----------------
__device__ float g_xn   [ROWS*CDIM];     // ln1(x)
__device__ float g_xrn  [ROWS*CDIM];     // ln1(x_reverse)
__device__ float g_q    [ROWS*GD];       // global q
__device__ float g_pool [BATCH*MPOOL*CDIM];
__device__ float g_kv   [BATCH*MPOOL*2*GD];
__device__ float g_gatt [ROWS*GD];       // global attn out
__device__ float g_cat  [ROWS*CDIM];     // [Gp out | Lp out]
__device__ float g_ql   [ROWS*LD];
__device__ float g_kvl  [ROWS*2*LD];
__device__ float g_latt [ROWS*LD];
__device__ float g_ln2  [ROWS*CDIM];
__device__ float g_h1   [ROWS*HID];
__device__ float g_h2   [ROWS*HID];

// ---------------- LayerNorm: one warp per 256-wide row ----------------
__global__ void ln_kernel(const float* __restrict__ x, const float* __restrict__ g,
                          const float* __restrict__ b, float* __restrict__ out, int rows)
{
    int gw   = (blockIdx.x * blockDim.x + threadIdx.x) >> 5;
    int lane = threadIdx.x & 31;
    if (gw >= rows) return;
    const float4* xr = (const float4*)(x + (size_t)gw * CDIM);
    float4 v0 = xr[lane];
    float4 v1 = xr[lane + 32];
    float s  = v0.x+v0.y+v0.z+v0.w + v1.x+v1.y+v1.z+v1.w;
    float ss = v0.x*v0.x+v0.y*v0.y+v0.z*v0.z+v0.w*v0.w
             + v1.x*v1.x+v1.y*v1.y+v1.z*v1.z+v1.w*v1.w;
    #pragma unroll
    for (int o = 16; o; o >>= 1) {
        s  += __shfl_xor_sync(0xffffffffu, s,  o);
        ss += __shfl_xor_sync(0xffffffffu, ss, o);
    }
    float mean = s * (1.0f/CDIM);
    float var  = ss * (1.0f/CDIM) - mean*mean;
    float inv  = rsqrtf(var + 1e-5f);
    const float4* g4 = (const float4*)g;
    const float4* b4 = (const float4*)b;
    float4 G0 = g4[lane], B0 = b4[lane], G1 = g4[lane+32], B1 = b4[lane+32];
    float4 o0, o1;
    o0.x = (v0.x-mean)*inv*G0.x + B0.x;  o0.y = (v0.y-mean)*inv*G0.y + B0.y;
    o0.z = (v0.z-mean)*inv*G0.z + B0.z;  o0.w = (v0.w-mean)*inv*G0.w + B0.w;
    o1.x = (v1.x-mean)*inv*G1.x + B1.x;  o1.y = (v1.y-mean)*inv*G1.y + B1.y;
    o1.z = (v1.z-mean)*inv*G1.z + B1.z;  o1.w = (v1.w-mean)*inv*G1.w + B1.w;
    float4* orow = (float4*)(out + (size_t)gw * CDIM);
    orow[lane]      = o0;
    orow[lane + 32] = o1;
}

// ---------------- 7x7 mean pooling: one thread per (b, grid, c) ----------------
__global__ void pool_kernel(const float* __restrict__ xrn, float* __restrict__ pooled)
{
    int t = blockIdx.x * blockDim.x + threadIdx.x;      // < 4*256*256
    int c = t & 255;
    int g = (t >> 8) & 255;
    int b = t >> 16;
    int gy = g >> 4, gx = g & 15;
    float s = 0.0f;
    #pragma unroll
    for (int py = 0; py < WSZ; py++) {
        int rowbase = (gy*WSZ + py) * HW + gx*WSZ;
        #pragma unroll
        for (int px = 0; px < WSZ; px++)
            s += xrn[((size_t)b*NTOK + rowbase + px) * CDIM + c];
    }
    pooled[t] = s * (1.0f/49.0f);
}

// ---------------- fp32 SGEMM: C[m, coff+n] = (add?) + A[M,K] @ B[K,Nc] + bias[n]
// 128x128x16 tile, 256 threads, 8x8 per thread. All dims multiples of tile dims.
__global__ void __launch_bounds__(256) gemm_kernel(
    const float* __restrict__ A, const float* __restrict__ Bm,
    const float* __restrict__ bias, const float* __restrict__ addsrc,
    float* __restrict__ C, int M, int Nc, int K, int ldc, int coff)
{
    __shared__ float As[16][128];
    __shared__ float Bs[16][128];
    const int tid = threadIdx.x;
    const int bm = blockIdx.y * 128;
    const int bn = blockIdx.x * 128;
    const int row0 = (tid / 16) * 8;
    const int col0 = (tid % 16) * 8;

    float acc[8][8];
    #pragma unroll
    for (int i = 0; i < 8; i++)
        #pragma unroll
        for (int j = 0; j < 8; j++) acc[i][j] = 0.0f;

    for (int k0 = 0; k0 < K; k0 += 16) {
        #pragma unroll
        for (int j = 0; j < 2; j++) {
            int lid = tid + j*256;
            int ar = lid >> 2, ac = (lid & 3) * 4;
            float4 av = *(const float4*)&A[(size_t)(bm+ar)*K + k0 + ac];
            As[ac+0][ar] = av.x; As[ac+1][ar] = av.y;
            As[ac+2][ar] = av.z; As[ac+3][ar] = av.w;
            int br = lid >> 5, bc = (lid & 31) * 4;
            *(float4*)&Bs[br][bc] = *(const float4*)&Bm[(size_t)(k0+br)*Nc + bn + bc];
        }
        __syncthreads();
        #pragma unroll
        for (int kk = 0; kk < 16; kk++) {
            float a[8], bv[8];
            *(float4*)&a[0]  = *(const float4*)&As[kk][row0];
            *(float4*)&a[4]  = *(const float4*)&As[kk][row0+4];
            *(float4*)&bv[0] = *(const float4*)&Bs[kk][col0];
            *(float4*)&bv[4] = *(const float4*)&Bs[kk][col0+4];
            #pragma unroll
            for (int i = 0; i < 8; i++)
                #pragma unroll
                for (int j = 0; j < 8; j++)
                    acc[i][j] = fmaf(a[i], bv[j], acc[i][j]);
        }
        __syncthreads();
    }

    #pragma unroll
    for (int i = 0; i < 8; i++) {
        size_t base = (size_t)(bm + row0 + i) * ldc + coff + bn + col0;
        #pragma unroll
        for (int jj = 0; jj < 8; jj += 4) {
            float4 bb = *(const float4*)&bias[bn + col0 + jj];
            float4 o;
            o.x = acc[i][jj+0] + bb.x;
            o.y = acc[i][jj+1] + bb.y;
            o.z = acc[i][jj+2] + bb.z;
            o.w = acc[i][jj+3] + bb.w;
            if (addsrc) {
                float4 sv = *(const float4*)&addsrc[base + jj];
                o.x += sv.x; o.y += sv.y; o.z += sv.z; o.w += sv.w;
            }
            *(float4*)&C[base + jj] = o;
        }
    }
}

// ---------------- global attention: block = (b, head, 128-query chunk) --------
// K/V for (b,h): 256 keys of 32 dims; processed in 2 chunks of 128 (smem 32KB).
__global__ void __launch_bounds__(128) gattn_kernel(
    const float* __restrict__ q, const float* __restrict__ kv, float* __restrict__ out)
{
    __shared__ float ks[128][HD];
    __shared__ float vs[128][HD];
    int bi = blockIdx.x;
    int qc = bi % (NTOK/128);
    int h  = (bi / (NTOK/128)) & (GH-1);
    int b  = bi / ((NTOK/128) * GH);
    int tid = threadIdx.x;
    int n   = qc*128 + tid;
    size_t qrow = (size_t)(b*NTOK + n) * GD + h*HD;

    float qreg[HD];
    {
        const float4* qp = (const float4*)&q[qrow];
        #pragma unroll
        for (int j = 0; j < 8; j++) {
            float4 t = qp[j];
            qreg[4*j+0]=t.x; qreg[4*j+1]=t.y; qreg[4*j+2]=t.z; qreg[4*j+3]=t.w;
        }
    }

    float mx = -INFINITY, l = 0.0f;
    float accv[HD];
    #pragma unroll
    for (int d = 0; d < HD; d++) accv[d] = 0.0f;

    for (int ch = 0; ch < 2; ch++) {
        // cooperative load of 128 keys + 128 values (float4 granularity)
        #pragma unroll
        for (int j = 0; j < 8; j++) {
            int f4 = tid + 128*j;              // < 1024
            int m  = f4 >> 3;
            int d4 = (f4 & 7) * 4;
            size_t kvrow = (size_t)(b*MPOOL + ch*128 + m) * (2*GD) + h*HD;
            float4 kvv = *(const float4*)&kv[kvrow + d4];
            float4 vvv = *(const float4*)&kv[kvrow + GD + d4];
            *(float4*)&ks[m][d4] = kvv;
            *(float4*)&vs[m][d4] = vvv;
        }
        __syncthreads();
        for (int m = 0; m < 128; m++) {
            float s = 0.0f;
            #pragma unroll
            for (int d = 0; d < HD; d++) s = fmaf(qreg[d], ks[m][d], s);
            float sc = s * ATT_SCALE;
            if (sc > mx) {
                float corr = __expf(mx - sc);   // 0 on first key
                l *= corr;
                #pragma unroll
                for (int d = 0; d < HD; d++) accv[d] *= corr;
                mx = sc;
            }
            float p = __expf(sc - mx);
            l += p;
            #pragma unroll
            for (int d = 0; d < HD; d++) accv[d] = fmaf(p, vs[m][d], accv[d]);
        }
        __syncthreads();
    }

    float inv = 1.0f / l;
    float4* op = (float4*)&out[qrow];
    #pragma unroll
    for (int j = 0; j < 8; j++) {
        float4 o;
        o.x = accv[4*j+0]*inv; o.y = accv[4*j+1]*inv;
        o.z = accv[4*j+2]*inv; o.w = accv[4*j+3]*inv;
        op[j] = o;
    }
}

// ---------------- local window attention: block = (b, window, head-pair) -------
__global__ void __launch_bounds__(128) lattn_kernel(
    const float* __restrict__ ql, const float* __restrict__ kvl, float* __restrict__ out)
{
    __shared__ float ks[2][49][HD];
    __shared__ float vs[2][49][HD];
    int bi = blockIdx.x;
    int hp = bi & 1;                 // head pair: heads hp*2, hp*2+1
    int wi = (bi >> 1) & 255;
    int b  = bi >> 9;
    int wy = wi >> 4, wx = wi & 15;
    int tid = threadIdx.x;

    // load K/V for 2 heads x 49 tokens (float4 granularity: 2*49*8 = 784 per array)
    for (int i = tid; i < 2*49*8; i += 128) {
        int d4 = (i & 7) * 4;
        int t  = (i >> 3) % 49;
        int hh = i / (49*8);
        int py = t / WSZ, px = t % WSZ;
        int n  = (wy*WSZ + py)*HW + wx*WSZ + px;
        size_t rowb = (size_t)(b*NTOK + n) * (2*LD) + (hp*2 + hh)*HD;
        *(float4*)&ks[hh][t][d4] = *(const float4*)&kvl[rowb + d4];
        *(float4*)&vs[hh][t][d4] = *(const float4*)&kvl[rowb + LD + d4];
    }
    __syncthreads();

    if (tid < 98) {
        int hh = tid / 49;
        int qi = tid % 49;
        int h  = hp*2 + hh;
        int py = qi / WSZ, px = qi % WSZ;
        int n  = (wy*WSZ + py)*HW + wx*WSZ + px;
        size_t qrow = (size_t)(b*NTOK + n) * LD + h*HD;

        float qreg[HD];
        const float4* qp = (const float4*)&ql[qrow];
        #pragma unroll
        for (int j = 0; j < 8; j++) {
            float4 t = qp[j];
            qreg[4*j+0]=t.x; qreg[4*j+1]=t.y; qreg[4*j+2]=t.z; qreg[4*j+3]=t.w;
        }

        float sc[49];
        float mx = -INFINITY;
        #pragma unroll
        for (int t = 0; t < 49; t++) {
            float s = 0.0f;
            #pragma unroll
            for (int d = 0; d < HD; d++) s = fmaf(qreg[d], ks[hh][t][d], s);
            s *= ATT_SCALE;
            sc[t] = s;
            mx = fmaxf(mx, s);
        }
        float l = 0.0f;
        #pragma unroll
        for (int t = 0; t < 49; t++) { sc[t] = __expf(sc[t] - mx); l += sc[t]; }
        float inv = 1.0f / l;

        float accv[HD];
        #pragma unroll
        for (int d = 0; d < HD; d++) accv[d] = 0.0f;
        #pragma unroll
        for (int t = 0; t < 49; t++) {
            float p = sc[t] * inv;
            #pragma unroll
            for (int d = 0; d < HD; d++) accv[d] = fmaf(p, vs[hh][t][d], accv[d]);
        }
        float4* op = (float4*)&out[qrow];
        #pragma unroll
        for (int j = 0; j < 8; j++) {
            float4 o;
            o.x = accv[4*j+0]; o.y = accv[4*j+1]; o.z = accv[4*j+2]; o.w = accv[4*j+3];
            op[j] = o;
        }
    }
}

// ---------------- residual add (float4) ----------------
__global__ void add_kernel(const float* __restrict__ a, const float* __restrict__ b,
                           float* __restrict__ out)
{
    int t = blockIdx.x * blockDim.x + threadIdx.x;
    float4 av = ((const float4*)a)[t];
    float4 bv = ((const float4*)b)[t];
    float4 o;
    o.x = av.x+bv.x; o.y = av.y+bv.y; o.z = av.z+bv.z; o.w = av.w+bv.w;
    ((float4*)out)[t] = o;
}

// ---------------- depthwise 3x3 conv (channels-last) + exact GELU --------------
__device__ __forceinline__ float gelu_exact(float v)
{
    return 0.5f * v * (1.0f + erff(v * 0.70710678118654752f));
}

__global__ void dwconv_gelu_kernel(const float* __restrict__ h, const float* __restrict__ w,
                                   const float* __restrict__ bias, float* __restrict__ out)
{
    int t = blockIdx.x * blockDim.x + threadIdx.x;  // < 4*112*112*256 (c-groups of 4)
    int c4 = t & 255;
    int p  = t >> 8;
    int xx = p % HW;
    int tmp = p / HW;
    int yy = tmp % HW;
    int bb = tmp / HW;
    int c  = c4 * 4;

    float wv[4][9];
    #pragma unroll
    for (int e = 0; e < 4; e++)
        #pragma unroll
        for (int k = 0; k < 9; k++)
            wv[e][k] = w[(c+e)*9 + k];

    float4 acc = *(const float4*)&bias[c];
    #pragma unroll
    for (int dy = 0; dy < 3; dy++) {
        int y2 = yy + dy - 1;
        if ((unsigned)y2 >= HW) continue;
        #pragma unroll
        for (int dx = 0; dx < 3; dx++) {
            int x2 = xx + dx - 1;
            if ((unsigned)x2 >= HW) continue;
            float4 v = *(const float4*)&h[((size_t)bb*NTOK + y2*HW + x2) * HID + c];
            int k = dy*3 + dx;
            acc.x = fmaf(v.x, wv[0][k], acc.x);
            acc.y = fmaf(v.y, wv[1][k], acc.y);
            acc.z = fmaf(v.z, wv[2][k], acc.z);
            acc.w = fmaf(v.w, wv[3][k], acc.w);
        }
    }
    acc.x = gelu_exact(acc.x); acc.y = gelu_exact(acc.y);
    acc.z = gelu_exact(acc.z); acc.w = gelu_exact(acc.w);
    *(float4*)&out[(size_t)t * 4] = acc;
}

// ---------------- launch ----------------
extern "C" void kernel_launch(void* const* d_in, const int* in_sizes, int n_in,
                              void* d_out, int out_size)
{
    const float* x     = (const float*)d_in[0];
    const float* xr    = (const float*)d_in[1];
    const float* g1    = (const float*)d_in[2];
    const float* b1    = (const float*)d_in[3];
    const float* g2    = (const float*)d_in[4];
    const float* b2    = (const float*)d_in[5];
    const float* Gq_w  = (const float*)d_in[6];
    const float* Gq_b  = (const float*)d_in[7];
    const float* Gkv_w = (const float*)d_in[8];
    const float* Gkv_b = (const float*)d_in[9];
    const float* Gp_w  = (const float*)d_in[10];
    const float* Gp_b  = (const float*)d_in[11];
    const float* Lq_w  = (const float*)d_in[12];
    const float* Lq_b  = (const float*)d_in[13];
    const float* Lkv_w = (const float*)d_in[14];
    const float* Lkv_b = (const float*)d_in[15];
    const float* Lp_w  = (const float*)d_in[16];
    const float* Lp_b  = (const float*)d_in[17];
    const float* fc1_w = (const float*)d_in[18];
    const float* fc1_b = (const float*)d_in[19];
    const float* dw_w  = (const float*)d_in[20];
    const float* dw_b  = (const float*)d_in[21];
    const float* fc2_w = (const float*)d_in[22];
    const float* fc2_b = (const float*)d_in[23];
    float* out = (float*)d_out;

    float *p_xn, *p_xrn, *p_q, *p_pool, *p_kv, *p_gatt, *p_cat,
          *p_ql, *p_kvl, *p_latt, *p_ln2, *p_h1, *p_h2;
    cudaGetSymbolAddress((void**)&p_xn,   g_xn);
    cudaGetSymbolAddress((void**)&p_xrn,  g_xrn);
    cudaGetSymbolAddress((void**)&p_q,    g_q);
    cudaGetSymbolAddress((void**)&p_pool, g_pool);
    cudaGetSymbolAddress((void**)&p_kv,   g_kv);
    cudaGetSymbolAddress((void**)&p_gatt, g_gatt);
    cudaGetSymbolAddress((void**)&p_cat,  g_cat);
    cudaGetSymbolAddress((void**)&p_ql,   g_ql);
    cudaGetSymbolAddress((void**)&p_kvl,  g_kvl);
    cudaGetSymbolAddress((void**)&p_latt, g_latt);
    cudaGetSymbolAddress((void**)&p_ln2,  g_ln2);
    cudaGetSymbolAddress((void**)&p_h1,   g_h1);
    cudaGetSymbolAddress((void**)&p_h2,   g_h2);

    // 1. LayerNorms
    ln_kernel<<<ROWS/8, 256>>>(x,  g1, b1, p_xn,  ROWS);
    ln_kernel<<<ROWS/8, 256>>>(xr, g1, b1, p_xrn, ROWS);

    // 2. Pool
    pool_kernel<<<(BATCH*MPOOL*CDIM)/256, 256>>>(p_xrn, p_pool);

    // 3. Projections
    gemm_kernel<<<dim3(1, ROWS/128), 256>>>(p_xn,  Gq_w,  Gq_b,  nullptr, p_q,   ROWS,  GD,    CDIM, GD,    0);
    gemm_kernel<<<dim3(2, (BATCH*MPOOL)/128), 256>>>(p_pool, Gkv_w, Gkv_b, nullptr, p_kv, BATCH*MPOOL, 2*GD, CDIM, 2*GD, 0);
    gemm_kernel<<<dim3(1, ROWS/128), 256>>>(p_xn,  Lq_w,  Lq_b,  nullptr, p_ql,  ROWS,  LD,    CDIM, LD,    0);
    gemm_kernel<<<dim3(2, ROWS/128), 256>>>(p_xrn, Lkv_w, Lkv_b, nullptr, p_kvl, ROWS,  2*LD,  CDIM, 2*LD,  0);

    // 4. Attentions
    gattn_kernel<<<BATCH*GH*(NTOK/128), 128>>>(p_q, p_kv, p_gatt);
    lattn_kernel<<<BATCH*256*2, 128>>>(p_ql, p_kvl, p_latt);

    // 5. Output projections into concat buffer
    gemm_kernel<<<dim3(1, ROWS/128), 256>>>(p_gatt, Gp_w, Gp_b, nullptr, p_cat, ROWS, GD, GD, CDIM, 0);
    gemm_kernel<<<dim3(1, ROWS/128), 256>>>(p_latt, Lp_w, Lp_b, nullptr, p_cat, ROWS, LD, LD, CDIM, GD);

    // 6. Residual: out = x + cat   (out holds x2)
    add_kernel<<<(ROWS*CDIM)/(256*4), 256>>>(x, p_cat, out);

    // 7. MLP
    ln_kernel<<<ROWS/8, 256>>>(out, g2, b2, p_ln2, ROWS);
    gemm_kernel<<<dim3(8, ROWS/128), 256>>>(p_ln2, fc1_w, fc1_b, nullptr, p_h1, ROWS, HID, CDIM, HID, 0);
    dwconv_gelu_kernel<<<(ROWS*CDIM)/256, 256>>>(p_h1, dw_w, dw_b, p_h2);
    // 8. FC2 + residual: out = out + h2 @ fc2_w + fc2_b
    gemm_kernel<<<dim3(2, ROWS/128), 256>>>(p_h2, fc2_w, fc2_b, out, out, ROWS, CDIM, HID, CDIM, 0);
}

// round 3
// speedup vs baseline: 2.1907x; 2.1907x over previous
#include <cuda_runtime.h>
#include <cuda_bf16.h>
#include <math.h>

// ---------------- problem constants ----------------
#define BATCH 4
#define HW    112
#define NTOK  12544
#define CDIM  256
#define GH    4
#define HD    32
#define GD    128
#define LD    128
#define HID   1024
#define WSZ   7
#define MPOOL 256
#define ROWS  (BATCH*NTOK)
#define ATT_SCALE 0.17677669529663687f

#define PADK  40
#define TILEB (128*PADK)

// ---------------- scratch (device globals; no allocation) ----------------
__device__ __align__(256) __nv_bfloat16 g_xn_h [ROWS*CDIM];
__device__ __align__(256) __nv_bfloat16 g_xn_l [ROWS*CDIM];
__device__ __align__(256) __nv_bfloat16 g_xrn_h[ROWS*CDIM];
__device__ __align__(256) __nv_bfloat16 g_xrn_l[ROWS*CDIM];
__device__ __align__(256) __nv_bfloat16 g_pool_h[BATCH*MPOOL*CDIM];
__device__ __align__(256) __nv_bfloat16 g_pool_l[BATCH*MPOOL*CDIM];
__device__ __align__(256) float g_q  [ROWS*GD];
__device__ __align__(256) float g_kv [BATCH*MPOOL*2*GD];
__device__ __align__(256) float g_ql [ROWS*LD];
__device__ __align__(256) float g_kvl[ROWS*2*LD];
__device__ __align__(256) __nv_bfloat16 g_gatt_h[ROWS*GD];
__device__ __align__(256) __nv_bfloat16 g_gatt_l[ROWS*GD];
__device__ __align__(256) __nv_bfloat16 g_latt_h[ROWS*LD];
__device__ __align__(256) __nv_bfloat16 g_latt_l[ROWS*LD];
__device__ __align__(256) float g_cat[ROWS*CDIM];
__device__ __align__(256) __nv_bfloat16 g_ln2_h[ROWS*CDIM];
__device__ __align__(256) __nv_bfloat16 g_ln2_l[ROWS*CDIM];
__device__ __align__(256) float g_h1 [ROWS*HID];
__device__ __align__(256) __nv_bfloat16 g_h2_h[ROWS*HID];
__device__ __align__(256) __nv_bfloat16 g_h2_l[ROWS*HID];
// transposed split weights: [N][K]
__device__ __align__(256) __nv_bfloat16 w_gq_h [GD*CDIM];
__device__ __align__(256) __nv_bfloat16 w_gq_l [GD*CDIM];
__device__ __align__(256) __nv_bfloat16 w_gkv_h[2*GD*CDIM];
__device__ __align__(256) __nv_bfloat16 w_gkv_l[2*GD*CDIM];
__device__ __align__(256) __nv_bfloat16 w_gp_h [GD*GD];
__device__ __align__(256) __nv_bfloat16 w_gp_l [GD*GD];
__device__ __align__(256) __nv_bfloat16 w_lq_h [LD*CDIM];
__device__ __align__(256) __nv_bfloat16 w_lq_l [LD*CDIM];
__device__ __align__(256) __nv_bfloat16 w_lkv_h[2*LD*CDIM];
__device__ __align__(256) __nv_bfloat16 w_lkv_l[2*LD*CDIM];
__device__ __align__(256) __nv_bfloat16 w_lp_h [LD*LD];
__device__ __align__(256) __nv_bfloat16 w_lp_l [LD*LD];
__device__ __align__(256) __nv_bfloat16 w_fc1_h[HID*CDIM];
__device__ __align__(256) __nv_bfloat16 w_fc1_l[HID*CDIM];
__device__ __align__(256) __nv_bfloat16 w_fc2_h[CDIM*HID];
__device__ __align__(256) __nv_bfloat16 w_fc2_l[CDIM*HID];

// ---------------- helpers ----------------
__device__ __forceinline__ void split_store4(__nv_bfloat16* ph, __nv_bfloat16* pl, float4 v)
{
    __nv_bfloat16 hx = __float2bfloat16(v.x);
    __nv_bfloat16 hy = __float2bfloat16(v.y);
    __nv_bfloat16 hz = __float2bfloat16(v.z);
    __nv_bfloat16 hw = __float2bfloat16(v.w);
    __nv_bfloat162 h0 = __nv_bfloat162(hx, hy);
    __nv_bfloat162 h1 = __nv_bfloat162(hz, hw);
    __nv_bfloat162 l0 = __nv_bfloat162(__float2bfloat16(v.x - __bfloat162float(hx)),
                                       __float2bfloat16(v.y - __bfloat162float(hy)));
    __nv_bfloat162 l1 = __nv_bfloat162(__float2bfloat16(v.z - __bfloat162float(hz)),
                                       __float2bfloat16(v.w - __bfloat162float(hw)));
    ((__nv_bfloat162*)ph)[0] = h0;
    ((__nv_bfloat162*)ph)[1] = h1;
    ((__nv_bfloat162*)pl)[0] = l0;
    ((__nv_bfloat162*)pl)[1] = l1;
}

__device__ __forceinline__ unsigned smem_u32(const void* p)
{
    return (unsigned)__cvta_generic_to_shared(p);
}

__device__ __forceinline__ void ldsm4(unsigned* r, unsigned addr)
{
    asm volatile("ldmatrix.sync.aligned.m8n8.x4.shared.b16 {%0,%1,%2,%3}, [%4];"
        : "=r"(r[0]), "=r"(r[1]), "=r"(r[2]), "=r"(r[3]) : "r"(addr));
}

__device__ __forceinline__ void mma_bf16(float* c, const unsigned* a, const unsigned* b)
{
    asm volatile("mma.sync.aligned.m16n8k16.row.col.f32.bf16.bf16.f32 "
        "{%0,%1,%2,%3},{%4,%5,%6,%7},{%8,%9},{%0,%1,%2,%3};"
        : "+f"(c[0]), "+f"(c[1]), "+f"(c[2]), "+f"(c[3])
        : "r"(a[0]), "r"(a[1]), "r"(a[2]), "r"(a[3]), "r"(b[0]), "r"(b[1]));
}

__device__ __forceinline__ void cpa16(unsigned saddr, const void* g)
{
    asm volatile("cp.async.cg.shared.global [%0], [%1], 16;" :: "r"(saddr), "l"(g) : "memory");
}

__device__ __forceinline__ void gemm_stage(
    __nv_bfloat16* sbase, int tid,
    const __nv_bfloat16* Ah, const __nv_bfloat16* Al,
    const __nv_bfloat16* Bh, const __nv_bfloat16* Bl,
    int bm, int bn, int K, int k0)
{
    __nv_bfloat16* sA0 = sbase;
    __nv_bfloat16* sA1 = sbase + TILEB;
    __nv_bfloat16* sB0 = sbase + 2*TILEB;
    __nv_bfloat16* sB1 = sbase + 3*TILEB;
    #pragma unroll
    for (int j = 0; j < 4; j++) {
        int u = tid + 128*j;
        int row = u >> 2;
        int qq = u & 3;
        int so = row * PADK + qq * 8;
        size_t gA = (size_t)(bm + row) * K + k0 + qq * 8;
        size_t gB = (size_t)(bn + row) * K + k0 + qq * 8;
        cpa16(smem_u32(sA0 + so), Ah + gA);
        cpa16(smem_u32(sA1 + so), Al + gA);
        cpa16(smem_u32(sB0 + so), Bh + gB);
        cpa16(smem_u32(sB1 + so), Bl + gB);
    }
}

// ---------------- weight transpose + split ----------------
__global__ void wtrans_kernel(const float* __restrict__ W, __nv_bfloat16* __restrict__ hi,
                              __nv_bfloat16* __restrict__ lo, int K, int N)
{
    int t = blockIdx.x * blockDim.x + threadIdx.x;
    if (t >= K * N) return;
    int n = t / K;
    int k = t - n * K;
    float v = W[(size_t)k * N + n];
    __nv_bfloat16 h = __float2bfloat16(v);
    hi[t] = h;
    lo[t] = __float2bfloat16(v - __bfloat162float(h));
}

// ---------------- LayerNorm ----------------
__global__ void ln_kernel(const float* __restrict__ x, const float* __restrict__ g,
                          const float* __restrict__ b,
                          __nv_bfloat16* __restrict__ oh, __nv_bfloat16* __restrict__ ol,
                          int rows)
{
    int gw   = (blockIdx.x * blockDim.x + threadIdx.x) >> 5;
    int lane = threadIdx.x & 31;
    if (gw >= rows) return;
    const float4* xr = (const float4*)(x + (size_t)gw * CDIM);
    float4 v0 = xr[lane];
    float4 v1 = xr[lane + 32];
    float s  = v0.x+v0.y+v0.z+v0.w + v1.x+v1.y+v1.z+v1.w;
    float ss = v0.x*v0.x+v0.y*v0.y+v0.z*v0.z+v0.w*v0.w
             + v1.x*v1.x+v1.y*v1.y+v1.z*v1.z+v1.w*v1.w;
    #pragma unroll
    for (int o = 16; o; o >>= 1) {
        s  += __shfl_xor_sync(0xffffffffu, s,  o);
        ss += __shfl_xor_sync(0xffffffffu, ss, o);
    }
    float mean = s * (1.0f/CDIM);
    float var  = ss * (1.0f/CDIM) - mean*mean;
    float inv  = rsqrtf(var + 1e-5f);
    const float4* g4 = (const float4*)g;
    const float4* b4 = (const float4*)b;
    float4 G0 = g4[lane];
    float4 B0 = b4[lane];
    float4 G1 = g4[lane+32];
    float4 B1 = b4[lane+32];
    float4 o0, o1;
    o0.x = (v0.x-mean)*inv*G0.x + B0.x;
    o0.y = (v0.y-mean)*inv*G0.y + B0.y;
    o0.z = (v0.z-mean)*inv*G0.z + B0.z;
    o0.w = (v0.w-mean)*inv*G0.w + B0.w;
    o1.x = (v1.x-mean)*inv*G1.x + B1.x;
    o1.y = (v1.y-mean)*inv*G1.y + B1.y;
    o1.z = (v1.z-mean)*inv*G1.z + B1.z;
    o1.w = (v1.w-mean)*inv*G1.w + B1.w;
    size_t base = (size_t)gw * CDIM + lane * 4;
    split_store4(oh + base,       ol + base,       o0);
    split_store4(oh + base + 128, ol + base + 128, o1);
}

// ---------------- 7x7 mean pooling ----------------
__global__ void pool_kernel(const __nv_bfloat16* __restrict__ xh,
                            const __nv_bfloat16* __restrict__ xl,
                            __nv_bfloat16* __restrict__ ph, __nv_bfloat16* __restrict__ pl)
{
    int t = blockIdx.x * blockDim.x + threadIdx.x;
    int c = t & 255;
    int g = (t >> 8) & 255;
    int b = t >> 16;
    int gy = g >> 4;
    int gx = g & 15;
    float s = 0.0f;
    #pragma unroll
    for (int py = 0; py < WSZ; py++) {
        int rowbase = (gy*WSZ + py) * HW + gx*WSZ;
        #pragma unroll
        for (int px = 0; px < WSZ; px++) {
            size_t idx = ((size_t)b*NTOK + rowbase + px) * CDIM + c;
            s += __bfloat162float(xh[idx]) + __bfloat162float(xl[idx]);
        }
    }
    float v = s * (1.0f/49.0f);
    __nv_bfloat16 h = __float2bfloat16(v);
    ph[t] = h;
    pl[t] = __float2bfloat16(v - __bfloat162float(h));
}

// ---------------- tensor-core bf16x3 GEMM ----------------
// C[m, coff+n] = (addsrc?) + (Ah+Al)[M,K] @ (Bh+Bl)[N,K]^T + bias[n]
__global__ void __launch_bounds__(128, 2) mma_gemm(
    const __nv_bfloat16* __restrict__ Ah, const __nv_bfloat16* __restrict__ Al,
    const __nv_bfloat16* __restrict__ Bh, const __nv_bfloat16* __restrict__ Bl,
    const float* __restrict__ bias, const float* __restrict__ addsrc,
    float* __restrict__ C, int M, int N, int K, int ldc, int coff)
{
    extern __shared__ __nv_bfloat16 sh[];
    int tid  = threadIdx.x;
    int lane = tid & 31;
    int warp = tid >> 5;
    int wm = (warp & 1) * 64;
    int wn = (warp >> 1) * 64;
    int bm = blockIdx.y * 128;
    int bn = blockIdx.x * 128;

    float acc[4][8][4];
    #pragma unroll
    for (int i = 0; i < 4; i++) {
        #pragma unroll
        for (int j = 0; j < 8; j++) {
            #pragma unroll
            for (int e = 0; e < 4; e++) {
                acc[i][j][e] = 0.0f;
            }
        }
    }

    int nIter = K >> 5;

    gemm_stage(sh, tid, Ah, Al, Bh, Bl, bm, bn, K, 0);
    asm volatile("cp.async.commit_group;" ::: "memory");

    for (int it = 0; it < nIter; it++) {
        int st = it & 1;
        if (it + 1 < nIter) {
            gemm_stage(sh + (st^1)*4*TILEB, tid, Ah, Al, Bh, Bl, bm, bn, K, (it+1) << 5);
            asm volatile("cp.async.commit_group;" ::: "memory");
            asm volatile("cp.async.wait_group 1;" ::: "memory");
        } else {
            asm volatile("cp.async.wait_group 0;" ::: "memory");
        }
        __syncthreads();

        const __nv_bfloat16* cA0 = sh + st*4*TILEB;
        const __nv_bfloat16* cA1 = cA0 + TILEB;
        const __nv_bfloat16* cB0 = cA0 + 2*TILEB;
        const __nv_bfloat16* cB1 = cA0 + 3*TILEB;

        #pragma unroll
        for (int kk = 0; kk < 2; kk++) {
            unsigned afh[4][4];
            unsigned afl[4][4];
            #pragma unroll
            for (int mi = 0; mi < 4; mi++) {
                int row = wm + mi*16 + (lane & 15);
                int col = kk*16 + (lane >> 4) * 8;
                ldsm4(afh[mi], smem_u32(cA0 + row*PADK + col));
                ldsm4(afl[mi], smem_u32(cA1 + row*PADK + col));
            }
            #pragma unroll
            for (int np = 0; np < 4; np++) {
                unsigned bfh[4];
                unsigned bfl[4];
                int row = wn + np*16 + (lane >> 4) * 8 + (lane & 7);
                int col = kk*16 + ((lane >> 3) & 1) * 8;
                ldsm4(bfh, smem_u32(cB0 + row*PADK + col));
                ldsm4(bfl, smem_u32(cB1 + row*PADK + col));
                #pragma unroll
                for (int mi = 0; mi < 4; mi++) {
                    mma_bf16(acc[mi][2*np],   afh[mi], &bfh[0]);
                    mma_bf16(acc[mi][2*np+1], afh[mi], &bfh[2]);
                }
                #pragma unroll
                for (int mi = 0; mi < 4; mi++) {
                    mma_bf16(acc[mi][2*np],   afh[mi], &bfl[0]);
                    mma_bf16(acc[mi][2*np+1], afh[mi], &bfl[2]);
                }
                #pragma unroll
                for (int mi = 0; mi < 4; mi++) {
                    mma_bf16(acc[mi][2*np],   afl[mi], &bfh[0]);
                    mma_bf16(acc[mi][2*np+1], afl[mi], &bfh[2]);
                }
            }
        }
        __syncthreads();
    }

    int gg = lane >> 2;
    int t2 = (lane & 3) * 2;
    #pragma unroll
    for (int mi = 0; mi < 4; mi++) {
        #pragma unroll
        for (int half = 0; half < 2; half++) {
            int row = bm + wm + mi*16 + gg + half*8;
            #pragma unroll
            for (int ni = 0; ni < 8; ni++) {
                int col = bn + wn + ni*8 + t2;
                float2 bv = *(const float2*)&bias[col];
                float v0 = acc[mi][ni][half*2 + 0] + bv.x;
                float v1 = acc[mi][ni][half*2 + 1] + bv.y;
                size_t off = (size_t)row * ldc + coff + col;
                if (addsrc) {
                    float2 sv = *(const float2*)&addsrc[off];
                    v0 += sv.x;
                    v1 += sv.y;
                }
                *(float2*)&C[off] = make_float2(v0, v1);
            }
        }
    }
}

// ---------------- global attention ----------------
__global__ void __launch_bounds__(128) gattn_kernel(
    const float* __restrict__ q, const float* __restrict__ kv,
    __nv_bfloat16* __restrict__ oh, __nv_bfloat16* __restrict__ ol)
{
    __shared__ float ks[128][HD];
    __shared__ float vs[128][HD];
    int bi = blockIdx.x;
    int qc = bi % (NTOK/128);
    int h  = (bi / (NTOK/128)) & (GH-1);
    int b  = bi / ((NTOK/128) * GH);
    int tid = threadIdx.x;
    int n   = qc*128 + tid;
    size_t qrow = (size_t)(b*NTOK + n) * GD + h*HD;

    float qreg[HD];
    const float4* qp = (const float4*)&q[qrow];
    #pragma unroll
    for (int j = 0; j < 8; j++) {
        float4 t = qp[j];
        qreg[4*j+0] = t.x;
        qreg[4*j+1] = t.y;
        qreg[4*j+2] = t.z;
        qreg[4*j+3] = t.w;
    }

    float mx = -INFINITY;
    float l = 0.0f;
    float accv[HD];
    #pragma unroll
    for (int d = 0; d < HD; d++) {
        accv[d] = 0.0f;
    }

    for (int ch = 0; ch < 2; ch++) {
        #pragma unroll
        for (int j = 0; j < 8; j++) {
            int f4 = tid + 128*j;
            int m  = f4 >> 3;
            int d4 = (f4 & 7) * 4;
            size_t kvrow = (size_t)(b*MPOOL + ch*128 + m) * (2*GD) + h*HD;
            *(float4*)&ks[m][d4] = *(const float4*)&kv[kvrow + d4];
            *(float4*)&vs[m][d4] = *(const float4*)&kv[kvrow + GD + d4];
        }
        __syncthreads();
        for (int m = 0; m < 128; m++) {
            float s = 0.0f;
            #pragma unroll
            for (int d = 0; d < HD; d++) {
                s = fmaf(qreg[d], ks[m][d], s);
            }
            float sc = s * ATT_SCALE;
            if (sc > mx) {
                float corr = __expf(mx - sc);
                l *= corr;
                #pragma unroll
                for (int d = 0; d < HD; d++) {
                    accv[d] *= corr;
                }
                mx = sc;
            }
            float p = __expf(sc - mx);
            l += p;
            #pragma unroll
            for (int d = 0; d < HD; d++) {
                accv[d] = fmaf(p, vs[m][d], accv[d]);
            }
        }
        __syncthreads();
    }

    float inv = 1.0f / l;
    #pragma unroll
    for (int j = 0; j < 8; j++) {
        float4 o = make_float4(accv[4*j+0]*inv, accv[4*j+1]*inv,
                               accv[4*j+2]*inv, accv[4*j+3]*inv);
        split_store4(oh + qrow + 4*j, ol + qrow + 4*j, o);
    }
}

// ---------------- local window attention ----------------
__global__ void __launch_bounds__(128) lattn_kernel(
    const float* __restrict__ ql, const float* __restrict__ kvl,
    __nv_bfloat16* __restrict__ oh, __nv_bfloat16* __restrict__ ol)
{
    __shared__ float ks[2][49][HD];
    __shared__ float vs[2][49][HD];
    int bi = blockIdx.x;
    int hp = bi & 1;
    int wi = (bi >> 1) & 255;
    int b  = bi >> 9;
    int wy = wi >> 4;
    int wx = wi & 15;
    int tid = threadIdx.x;

    for (int i = tid; i < 2*49*8; i += 128) {
        int d4 = (i & 7) * 4;
        int t  = (i >> 3) % 49;
        int hh = i / (49*8);
        int py = t / WSZ;
        int px = t % WSZ;
        int n  = (wy*WSZ + py)*HW + wx*WSZ + px;
        size_t rowb = (size_t)(b*NTOK + n) * (2*LD) + (hp*2 + hh)*HD;
        *(float4*)&ks[hh][t][d4] = *(const float4*)&kvl[rowb + d4];
        *(float4*)&vs[hh][t][d4] = *(const float4*)&kvl[rowb + LD + d4];
    }
    __syncthreads();

    if (tid < 98) {
        int hh = tid / 49;
        int qi = tid % 49;
        int h  = hp*2 + hh;
        int py = qi / WSZ;
        int px = qi % WSZ;
        int n  = (wy*WSZ + py)*HW + wx*WSZ + px;
        size_t qrow = (size_t)(b*NTOK + n) * LD + h*HD;

        float qreg[HD];
        const float4* qp = (const float4*)&ql[qrow];
        #pragma unroll
        for (int j = 0; j < 8; j++) {
            float4 t = qp[j];
            qreg[4*j+0] = t.x;
            qreg[4*j+1] = t.y;
            qreg[4*j+2] = t.z;
            qreg[4*j+3] = t.w;
        }

        float sc[49];
        float mx = -INFINITY;
        #pragma unroll
        for (int t = 0; t < 49; t++) {
            float s = 0.0f;
            #pragma unroll
            for (int d = 0; d < HD; d++) {
                s = fmaf(qreg[d], ks[hh][t][d], s);
            }
            s *= ATT_SCALE;
            sc[t] = s;
            mx = fmaxf(mx, s);
        }
        float l = 0.0f;
        #pragma unroll
        for (int t = 0; t < 49; t++) {
            sc[t] = __expf(sc[t] - mx);
            l += sc[t];
        }
        float inv = 1.0f / l;

        float accv[HD];
        #pragma unroll
        for (int d = 0; d < HD; d++) {
            accv[d] = 0.0f;
        }
        #pragma unroll
        for (int t = 0; t < 49; t++) {
            float p = sc[t] * inv;
            #pragma unroll
            for (int d = 0; d < HD; d++) {
                accv[d] = fmaf(p, vs[hh][t][d], accv[d]);
            }
        }
        #pragma unroll
        for (int j = 0; j < 8; j++) {
            float4 o = make_float4(accv[4*j+0], accv[4*j+1], accv[4*j+2], accv[4*j+3]);
            split_store4(oh + qrow + 4*j, ol + qrow + 4*j, o);
        }
    }
}

// ---------------- residual add ----------------
__global__ void add_kernel(const float* __restrict__ a, const float* __restrict__ b,
                           float* __restrict__ out)
{
    int t = blockIdx.x * blockDim.x + threadIdx.x;
    float4 av = ((const float4*)a)[t];
    float4 bv = ((const float4*)b)[t];
    ((float4*)out)[t] = make_float4(av.x+bv.x, av.y+bv.y, av.z+bv.z, av.w+bv.w);
}

// ---------------- depthwise 3x3 conv + exact GELU ----------------
__device__ __forceinline__ float gelu_exact(float v)
{
    return 0.5f * v * (1.0f + erff(v * 0.70710678118654752f));
}

__global__ void dwconv_gelu_kernel(const float* __restrict__ h, const float* __restrict__ w,
                                   const float* __restrict__ bias,
                                   __nv_bfloat16* __restrict__ oh, __nv_bfloat16* __restrict__ ol)
{
    int t = blockIdx.x * blockDim.x + threadIdx.x;
    int c4 = t & 255;
    int p  = t >> 8;
    int xx = p % HW;
    int tmp = p / HW;
    int yy = tmp % HW;
    int bb = tmp / HW;
    int c  = c4 * 4;

    float wv[4][9];
    #pragma unroll
    for (int e = 0; e < 4; e++) {
        #pragma unroll
        for (int k = 0; k < 9; k++) {
            wv[e][k] = w[(c+e)*9 + k];
        }
    }

    float4 acc = *(const float4*)&bias[c];
    #pragma unroll
    for (int dy = 0; dy < 3; dy++) {
        int y2 = yy + dy - 1;
        if ((unsigned)y2 >= HW) continue;
        #pragma unroll
        for (int dx = 0; dx < 3; dx++) {
            int x2 = xx + dx - 1;
            if ((unsigned)x2 >= HW) continue;
            float4 v = *(const float4*)&h[((size_t)bb*NTOK + y2*HW + x2) * HID + c];
            int k = dy*3 + dx;
            acc.x = fmaf(v.x, wv[0][k], acc.x);
            acc.y = fmaf(v.y, wv[1][k], acc.y);
            acc.z = fmaf(v.z, wv[2][k], acc.z);
            acc.w = fmaf(v.w, wv[3][k], acc.w);
        }
    }
    acc.x = gelu_exact(acc.x);
    acc.y = gelu_exact(acc.y);
    acc.z = gelu_exact(acc.z);
    acc.w = gelu_exact(acc.w);
    split_store4(oh + (size_t)t*4, ol + (size_t)t*4, acc);
}

// ---------------- launch ----------------
extern "C" void kernel_launch(void* const* d_in, const int* in_sizes, int n_in,
                              void* d_out, int out_size)
{
    const float* x     = (const float*)d_in[0];
    const float* xr    = (const float*)d_in[1];
    const float* g1    = (const float*)d_in[2];
    const float* b1    = (const float*)d_in[3];
    const float* g2    = (const float*)d_in[4];
    const float* b2    = (const float*)d_in[5];
    const float* Gq_w  = (const float*)d_in[6];
    const float* Gq_b  = (const float*)d_in[7];
    const float* Gkv_w = (const float*)d_in[8];
    const float* Gkv_b = (const float*)d_in[9];
    const float* Gp_w  = (const float*)d_in[10];
    const float* Gp_b  = (const float*)d_in[11];
    const float* Lq_w  = (const float*)d_in[12];
    const float* Lq_b  = (const float*)d_in[13];
    const float* Lkv_w = (const float*)d_in[14];
    const float* Lkv_b = (const float*)d_in[15];
    const float* Lp_w  = (const float*)d_in[16];
    const float* Lp_b  = (const float*)d_in[17];
    const float* fc1_w = (const float*)d_in[18];
    const float* fc1_b = (const float*)d_in[19];
    const float* dw_w  = (const float*)d_in[20];
    const float* dw_b  = (const float*)d_in[21];
    const float* fc2_w = (const float*)d_in[22];
    const float* fc2_b = (const float*)d_in[23];
    float* out = (float*)d_out;

    __nv_bfloat16 *p_xn_h;
    __nv_bfloat16 *p_xn_l;
    __nv_bfloat16 *p_xrn_h;
    __nv_bfloat16 *p_xrn_l;
    __nv_bfloat16 *p_pool_h;
    __nv_bfloat16 *p_pool_l;
    __nv_bfloat16 *p_gatt_h;
    __nv_bfloat16 *p_gatt_l;
    __nv_bfloat16 *p_latt_h;
    __nv_bfloat16 *p_latt_l;
    __nv_bfloat16 *p_ln2_h;
    __nv_bfloat16 *p_ln2_l;
    __nv_bfloat16 *p_h2_h;
    __nv_bfloat16 *p_h2_l;
    float *p_q;
    float *p_kv;
    float *p_ql;
    float *p_kvl;
    float *p_cat;
    float *p_h1;
    __nv_bfloat16 *p_wgq_h;
    __nv_bfloat16 *p_wgq_l;
    __nv_bfloat16 *p_wgkv_h;
    __nv_bfloat16 *p_wgkv_l;
    __nv_bfloat16 *p_wgp_h;
    __nv_bfloat16 *p_wgp_l;
    __nv_bfloat16 *p_wlq_h;
    __nv_bfloat16 *p_wlq_l;
    __nv_bfloat16 *p_wlkv_h;
    __nv_bfloat16 *p_wlkv_l;
    __nv_bfloat16 *p_wlp_h;
    __nv_bfloat16 *p_wlp_l;
    __nv_bfloat16 *p_wfc1_h;
    __nv_bfloat16 *p_wfc1_l;
    __nv_bfloat16 *p_wfc2_h;
    __nv_bfloat16 *p_wfc2_l;

    cudaGetSymbolAddress((void**)&p_xn_h, g_xn_h);
    cudaGetSymbolAddress((void**)&p_xn_l, g_xn_l);
    cudaGetSymbolAddress((void**)&p_xrn_h, g_xrn_h);
    cudaGetSymbolAddress((void**)&p_xrn_l, g_xrn_l);
    cudaGetSymbolAddress((void**)&p_pool_h, g_pool_h);
    cudaGetSymbolAddress((void**)&p_pool_l, g_pool_l);
    cudaGetSymbolAddress((void**)&p_gatt_h, g_gatt_h);
    cudaGetSymbolAddress((void**)&p_gatt_l, g_gatt_l);
    cudaGetSymbolAddress((void**)&p_latt_h, g_latt_h);
    cudaGetSymbolAddress((void**)&p_latt_l, g_latt_l);
    cudaGetSymbolAddress((void**)&p_ln2_h, g_ln2_h);
    cudaGetSymbolAddress((void**)&p_ln2_l, g_ln2_l);
    cudaGetSymbolAddress((void**)&p_h2_h, g_h2_h);
    cudaGetSymbolAddress((void**)&p_h2_l, g_h2_l);
    cudaGetSymbolAddress((void**)&p_q, g_q);
    cudaGetSymbolAddress((void**)&p_kv, g_kv);
    cudaGetSymbolAddress((void**)&p_ql, g_ql);
    cudaGetSymbolAddress((void**)&p_kvl, g_kvl);
    cudaGetSymbolAddress((void**)&p_cat, g_cat);
    cudaGetSymbolAddress((void**)&p_h1, g_h1);
    cudaGetSymbolAddress((void**)&p_wgq_h, w_gq_h);
    cudaGetSymbolAddress((void**)&p_wgq_l, w_gq_l);
    cudaGetSymbolAddress((void**)&p_wgkv_h, w_gkv_h);
    cudaGetSymbolAddress((void**)&p_wgkv_l, w_gkv_l);
    cudaGetSymbolAddress((void**)&p_wgp_h, w_gp_h);
    cudaGetSymbolAddress((void**)&p_wgp_l, w_gp_l);
    cudaGetSymbolAddress((void**)&p_wlq_h, w_lq_h);
    cudaGetSymbolAddress((void**)&p_wlq_l, w_lq_l);
    cudaGetSymbolAddress((void**)&p_wlkv_h, w_lkv_h);
    cudaGetSymbolAddress((void**)&p_wlkv_l, w_lkv_l);
    cudaGetSymbolAddress((void**)&p_wlp_h, w_lp_h);
    cudaGetSymbolAddress((void**)&p_wlp_l, w_lp_l);
    cudaGetSymbolAddress((void**)&p_wfc1_h, w_fc1_h);
    cudaGetSymbolAddress((void**)&p_wfc1_l, w_fc1_l);
    cudaGetSymbolAddress((void**)&p_wfc2_h, w_fc2_h);
    cudaGetSymbolAddress((void**)&p_wfc2_l, w_fc2_l);

    const int SMEM = 2 * 4 * TILEB * (int)sizeof(__nv_bfloat16);   // 81920
    cudaFuncSetAttribute(mma_gemm, cudaFuncAttributeMaxDynamicSharedMemorySize, SMEM);

    // 0. weight transpose + split
    wtrans_kernel<<<(CDIM*GD+255)/256,   256>>>(Gq_w,  p_wgq_h,  p_wgq_l,  CDIM, GD);
    wtrans_kernel<<<(CDIM*2*GD+255)/256, 256>>>(Gkv_w, p_wgkv_h, p_wgkv_l, CDIM, 2*GD);
    wtrans_kernel<<<(GD*GD+255)/256,     256>>>(Gp_w,  p_wgp_h,  p_wgp_l,  GD,   GD);
    wtrans_kernel<<<(CDIM*LD+255)/256,   256>>>(Lq_w,  p_wlq_h,  p_wlq_l,  CDIM, LD);
    wtrans_kernel<<<(CDIM*2*LD+255)/256, 256>>>(Lkv_w, p_wlkv_h, p_wlkv_l, CDIM, 2*LD);
    wtrans_kernel<<<(LD*LD+255)/256,     256>>>(Lp_w,  p_wlp_h,  p_wlp_l,  LD,   LD);
    wtrans_kernel<<<(CDIM*HID+255)/256,  256>>>(fc1_w, p_wfc1_h, p_wfc1_l, CDIM, HID);
    wtrans_kernel<<<(HID*CDIM+255)/256,  256>>>(fc2_w, p_wfc2_h, p_wfc2_l, HID,  CDIM);

    // 1. LayerNorms
    ln_kernel<<<ROWS/8, 256>>>(x,  g1, b1, p_xn_h,  p_xn_l,  ROWS);
    ln_kernel<<<ROWS/8, 256>>>(xr, g1, b1, p_xrn_h, p_xrn_l, ROWS);

    // 2. Pool
    pool_kernel<<<(BATCH*MPOOL*CDIM)/256, 256>>>(p_xrn_h, p_xrn_l, p_pool_h, p_pool_l);

    // 3. Projections
    mma_gemm<<<dim3(1, ROWS/128), 128, SMEM>>>(p_xn_h, p_xn_l, p_wgq_h, p_wgq_l, Gq_b, 0,
                                               p_q, ROWS, GD, CDIM, GD, 0);
    mma_gemm<<<dim3(2, (BATCH*MPOOL)/128), 128, SMEM>>>(p_pool_h, p_pool_l, p_wgkv_h, p_wgkv_l, Gkv_b, 0,
                                               p_kv, BATCH*MPOOL, 2*GD, CDIM, 2*GD, 0);
    mma_gemm<<<dim3(1, ROWS/128), 128, SMEM>>>(p_xn_h, p_xn_l, p_wlq_h, p_wlq_l, Lq_b, 0,
                                               p_ql, ROWS, LD, CDIM, LD, 0);
    mma_gemm<<<dim3(2, ROWS/128), 128, SMEM>>>(p_xrn_h, p_xrn_l, p_wlkv_h, p_wlkv_l, Lkv_b, 0,
                                               p_kvl, ROWS, 2*LD, CDIM, 2*LD, 0);

    // 4. Attentions
    gattn_kernel<<<BATCH*GH*(NTOK/128), 128>>>(p_q, p_kv, p_gatt_h, p_gatt_l);
    lattn_kernel<<<BATCH*256*2, 128>>>(p_ql, p_kvl, p_latt_h, p_latt_l);

    // 5. Output projections into concat buffer
    mma_gemm<<<dim3(1, ROWS/128), 128, SMEM>>>(p_gatt_h, p_gatt_l, p_wgp_h, p_wgp_l, Gp_b, 0,
                                               p_cat, ROWS, GD, GD, CDIM, 0);
    mma_gemm<<<dim3(1, ROWS/128), 128, SMEM>>>(p_latt_h, p_latt_l, p_wlp_h, p_wlp_l, Lp_b, 0,
                                               p_cat, ROWS, LD, LD, CDIM, GD);

    // 6. Residual: out = x + cat
    add_kernel<<<(ROWS*CDIM)/(256*4), 256>>>(x, p_cat, out);

    // 7. MLP
    ln_kernel<<<ROWS/8, 256>>>(out, g2, b2, p_ln2_h, p_ln2_l, ROWS);
    mma_gemm<<<dim3(8, ROWS/128), 128, SMEM>>>(p_ln2_h, p_ln2_l, p_wfc1_h, p_wfc1_l, fc1_b, 0,
                                               p_h1, ROWS, HID, CDIM, HID, 0);
    dwconv_gelu_kernel<<<(ROWS*CDIM)/256, 256>>>(p_h1, dw_w, dw_b, p_h2_h, p_h2_l);
    // 8. FC2 + residual
    mma_gemm<<<dim3(2, ROWS/128), 128, SMEM>>>(p_h2_h, p_h2_l, p_wfc2_h, p_wfc2_l, fc2_b, out,
                                               out, ROWS, CDIM, HID, CDIM, 0);
}

// round 5
// speedup vs baseline: 2.5302x; 1.1550x over previous
#include <cuda_runtime.h>
#include <cuda_bf16.h>
#include <math.h>

// ---------------- problem constants ----------------
#define BATCH 4
#define HW    112
#define NTOK  12544
#define CDIM  256
#define GH    4
#define HD    32
#define GD    128
#define LD    128
#define HID   1024
#define WSZ   7
#define MPOOL 256
#define ROWS  (BATCH*NTOK)
#define ATT_SCALE 0.17677669529663687f

#define PADK  40
#define TILEB (128*PADK)

// ---------------- scratch (device globals; no allocation) ----------------
__device__ __align__(256) __nv_bfloat16 g_xn_h [ROWS*CDIM];
__device__ __align__(256) __nv_bfloat16 g_xn_l [ROWS*CDIM];
__device__ __align__(256) __nv_bfloat16 g_xrn_h[ROWS*CDIM];
__device__ __align__(256) __nv_bfloat16 g_xrn_l[ROWS*CDIM];
__device__ __align__(256) __nv_bfloat16 g_pool_h[BATCH*MPOOL*CDIM];
__device__ __align__(256) __nv_bfloat16 g_pool_l[BATCH*MPOOL*CDIM];
__device__ __align__(256) float g_q  [ROWS*GD];
__device__ __align__(256) float g_kv [BATCH*MPOOL*2*GD];
__device__ __align__(256) float g_ql [ROWS*LD];
__device__ __align__(256) float g_kvl[ROWS*2*LD];
__device__ __align__(256) __nv_bfloat16 g_gatt_h[ROWS*GD];
__device__ __align__(256) __nv_bfloat16 g_gatt_l[ROWS*GD];
__device__ __align__(256) __nv_bfloat16 g_latt_h[ROWS*LD];
__device__ __align__(256) __nv_bfloat16 g_latt_l[ROWS*LD];
__device__ __align__(256) float g_cat[ROWS*CDIM];
__device__ __align__(256) __nv_bfloat16 g_ln2_h[ROWS*CDIM];
__device__ __align__(256) __nv_bfloat16 g_ln2_l[ROWS*CDIM];
__device__ __align__(256) float g_h1 [ROWS*HID];
__device__ __align__(256) __nv_bfloat16 g_h2_h[ROWS*HID];
__device__ __align__(256) __nv_bfloat16 g_h2_l[ROWS*HID];
// transposed split weights: [N][K]
__device__ __align__(256) __nv_bfloat16 w_gq_h [GD*CDIM];
__device__ __align__(256) __nv_bfloat16 w_gq_l [GD*CDIM];
__device__ __align__(256) __nv_bfloat16 w_gkv_h[2*GD*CDIM];
__device__ __align__(256) __nv_bfloat16 w_gkv_l[2*GD*CDIM];
__device__ __align__(256) __nv_bfloat16 w_gp_h [GD*GD];
__device__ __align__(256) __nv_bfloat16 w_gp_l [GD*GD];
__device__ __align__(256) __nv_bfloat16 w_lq_h [LD*CDIM];
__device__ __align__(256) __nv_bfloat16 w_lq_l [LD*CDIM];
__device__ __align__(256) __nv_bfloat16 w_lkv_h[2*LD*CDIM];
__device__ __align__(256) __nv_bfloat16 w_lkv_l[2*LD*CDIM];
__device__ __align__(256) __nv_bfloat16 w_lp_h [LD*LD];
__device__ __align__(256) __nv_bfloat16 w_lp_l [LD*LD];
__device__ __align__(256) __nv_bfloat16 w_fc1_h[HID*CDIM];
__device__ __align__(256) __nv_bfloat16 w_fc1_l[HID*CDIM];
__device__ __align__(256) __nv_bfloat16 w_fc2_h[CDIM*HID];
__device__ __align__(256) __nv_bfloat16 w_fc2_l[CDIM*HID];

// ---------------- helpers ----------------
__device__ __forceinline__ void split_store4(__nv_bfloat16* ph, __nv_bfloat16* pl, float4 v)
{
    __nv_bfloat16 hx = __float2bfloat16(v.x);
    __nv_bfloat16 hy = __float2bfloat16(v.y);
    __nv_bfloat16 hz = __float2bfloat16(v.z);
    __nv_bfloat16 hw = __float2bfloat16(v.w);
    __nv_bfloat162 h0 = __nv_bfloat162(hx, hy);
    __nv_bfloat162 h1 = __nv_bfloat162(hz, hw);
    __nv_bfloat162 l0 = __nv_bfloat162(__float2bfloat16(v.x - __bfloat162float(hx)),
                                       __float2bfloat16(v.y - __bfloat162float(hy)));
    __nv_bfloat162 l1 = __nv_bfloat162(__float2bfloat16(v.z - __bfloat162float(hz)),
                                       __float2bfloat16(v.w - __bfloat162float(hw)));
    ((__nv_bfloat162*)ph)[0] = h0;
    ((__nv_bfloat162*)ph)[1] = h1;
    ((__nv_bfloat162*)pl)[0] = l0;
    ((__nv_bfloat162*)pl)[1] = l1;
}

__device__ __forceinline__ unsigned smem_u32(const void* p)
{
    return (unsigned)__cvta_generic_to_shared(p);
}

__device__ __forceinline__ void ldsm4(unsigned* r, unsigned addr)
{
    asm volatile("ldmatrix.sync.aligned.m8n8.x4.shared.b16 {%0,%1,%2,%3}, [%4];"
        : "=r"(r[0]), "=r"(r[1]), "=r"(r[2]), "=r"(r[3]) : "r"(addr));
}

__device__ __forceinline__ void mma_bf16(float* c, const unsigned* a, const unsigned* b)
{
    asm volatile("mma.sync.aligned.m16n8k16.row.col.f32.bf16.bf16.f32 "
        "{%0,%1,%2,%3},{%4,%5,%6,%7},{%8,%9},{%0,%1,%2,%3};"
        : "+f"(c[0]), "+f"(c[1]), "+f"(c[2]), "+f"(c[3])
        : "r"(a[0]), "r"(a[1]), "r"(a[2]), "r"(a[3]), "r"(b[0]), "r"(b[1]));
}

__device__ __forceinline__ void cpa16(unsigned saddr, const void* g)
{
    asm volatile("cp.async.cg.shared.global [%0], [%1], 16;" :: "r"(saddr), "l"(g) : "memory");
}

// ---- packed f32x2 math (Blackwell FFMA2) ----
__device__ __forceinline__ void fma2(unsigned long long& d, unsigned long long a,
                                     unsigned long long b)
{
    asm("fma.rn.f32x2 %0, %1, %2, %0;" : "+l"(d) : "l"(a), "l"(b));
}

__device__ __forceinline__ void mul2(unsigned long long& d, unsigned long long c)
{
    asm("mul.rn.f32x2 %0, %0, %1;" : "+l"(d) : "l"(c));
}

__device__ __forceinline__ unsigned long long pack2(float x)
{
    unsigned long long r;
    asm("mov.b64 %0, {%1, %1};" : "=l"(r) : "f"(x));
    return r;
}

__device__ __forceinline__ float2 unpack2(unsigned long long v)
{
    float2 f;
    asm("mov.b64 {%0, %1}, %2;" : "=f"(f.x), "=f"(f.y) : "l"(v));
    return f;
}

__device__ __forceinline__ void gemm_stage(
    __nv_bfloat16* sbase, int tid,
    const __nv_bfloat16* Ah, const __nv_bfloat16* Al,
    const __nv_bfloat16* Bh, const __nv_bfloat16* Bl,
    int bm, int bn, int K, int k0)
{
    __nv_bfloat16* sA0 = sbase;
    __nv_bfloat16* sA1 = sbase + TILEB;
    __nv_bfloat16* sB0 = sbase + 2*TILEB;
    __nv_bfloat16* sB1 = sbase + 3*TILEB;
    #pragma unroll
    for (int j = 0; j < 4; j++) {
        int u = tid + 128*j;
        int row = u >> 2;
        int qq = u & 3;
        int so = row * PADK + qq * 8;
        size_t gA = (size_t)(bm + row) * K + k0 + qq * 8;
        size_t gB = (size_t)(bn + row) * K + k0 + qq * 8;
        cpa16(smem_u32(sA0 + so), Ah + gA);
        cpa16(smem_u32(sA1 + so), Al + gA);
        cpa16(smem_u32(sB0 + so), Bh + gB);
        cpa16(smem_u32(sB1 + so), Bl + gB);
    }
}

// ---------------- single-launch weight transpose + split ----------------
__device__ __forceinline__ void wt_one(const float* W, __nv_bfloat16* hi,
                                       __nv_bfloat16* lo, int K, int t)
{
    int n = t / K;
    int k = t - n * K;
    int N;
    // N derived from caller context is not needed: W indexed [k*N + n] -> pass stride
    // (handled by caller passing N via Kn trick below)
    (void)N;
    // placeholder; real work in wt_one2
    (void)W; (void)hi; (void)lo; (void)k; (void)n;
}

__device__ __forceinline__ void wt_do(const float* W, __nv_bfloat16* hi,
                                      __nv_bfloat16* lo, int K, int N, int t)
{
    int n = t / K;
    int k = t - n * K;
    float v = W[(size_t)k * N + n];
    __nv_bfloat16 h = __float2bfloat16(v);
    hi[t] = h;
    lo[t] = __float2bfloat16(v - __bfloat162float(h));
}

__global__ void wtrans_all(const float* __restrict__ Gq, const float* __restrict__ Gkv,
                           const float* __restrict__ Gp, const float* __restrict__ Lq,
                           const float* __restrict__ Lkv, const float* __restrict__ Lp,
                           const float* __restrict__ fc1, const float* __restrict__ fc2)
{
    int t = blockIdx.x * blockDim.x + threadIdx.x;
    if (t < 32768) {
        wt_do(Gq, w_gq_h, w_gq_l, CDIM, GD, t);
    } else if (t < 98304) {
        wt_do(Gkv, w_gkv_h, w_gkv_l, CDIM, 2*GD, t - 32768);
    } else if (t < 114688) {
        wt_do(Gp, w_gp_h, w_gp_l, GD, GD, t - 98304);
    } else if (t < 147456) {
        wt_do(Lq, w_lq_h, w_lq_l, CDIM, LD, t - 114688);
    } else if (t < 212992) {
        wt_do(Lkv, w_lkv_h, w_lkv_l, CDIM, 2*LD, t - 147456);
    } else if (t < 229376) {
        wt_do(Lp, w_lp_h, w_lp_l, LD, LD, t - 212992);
    } else if (t < 491520) {
        wt_do(fc1, w_fc1_h, w_fc1_l, CDIM, HID, t - 229376);
    } else if (t < 753664) {
        wt_do(fc2, w_fc2_h, w_fc2_l, HID, CDIM, t - 491520);
    }
}

// ---------------- LayerNorm (ln1) ----------------
__global__ void ln_kernel(const float* __restrict__ x, const float* __restrict__ g,
                          const float* __restrict__ b,
                          __nv_bfloat16* __restrict__ oh, __nv_bfloat16* __restrict__ ol,
                          int rows)
{
    int gw   = (blockIdx.x * blockDim.x + threadIdx.x) >> 5;
    int lane = threadIdx.x & 31;
    if (gw >= rows) return;
    const float4* xr = (const float4*)(x + (size_t)gw * CDIM);
    float4 v0 = xr[lane];
    float4 v1 = xr[lane + 32];
    float s  = v0.x+v0.y+v0.z+v0.w + v1.x+v1.y+v1.z+v1.w;
    float ss = v0.x*v0.x+v0.y*v0.y+v0.z*v0.z+v0.w*v0.w
             + v1.x*v1.x+v1.y*v1.y+v1.z*v1.z+v1.w*v1.w;
    #pragma unroll
    for (int o = 16; o; o >>= 1) {
        s  += __shfl_xor_sync(0xffffffffu, s,  o);
        ss += __shfl_xor_sync(0xffffffffu, ss, o);
    }
    float mean = s * (1.0f/CDIM);
    float var  = ss * (1.0f/CDIM) - mean*mean;
    float inv  = rsqrtf(var + 1e-5f);
    const float4* g4 = (const float4*)g;
    const float4* b4 = (const float4*)b;
    float4 G0 = g4[lane];
    float4 B0 = b4[lane];
    float4 G1 = g4[lane+32];
    float4 B1 = b4[lane+32];
    float4 o0, o1;
    o0.x = (v0.x-mean)*inv*G0.x + B0.x;
    o0.y = (v0.y-mean)*inv*G0.y + B0.y;
    o0.z = (v0.z-mean)*inv*G0.z + B0.z;
    o0.w = (v0.w-mean)*inv*G0.w + B0.w;
    o1.x = (v1.x-mean)*inv*G1.x + B1.x;
    o1.y = (v1.y-mean)*inv*G1.y + B1.y;
    o1.z = (v1.z-mean)*inv*G1.z + B1.z;
    o1.w = (v1.w-mean)*inv*G1.w + B1.w;
    size_t base = (size_t)gw * CDIM + lane * 4;
    split_store4(oh + base,       ol + base,       o0);
    split_store4(oh + base + 128, ol + base + 128, o1);
}

// ---------------- fused residual add + LayerNorm (ln2) ----------------
__global__ void addln_kernel(const float* __restrict__ x, const float* __restrict__ cat,
                             const float* __restrict__ g, const float* __restrict__ b,
                             float* __restrict__ out,
                             __nv_bfloat16* __restrict__ oh, __nv_bfloat16* __restrict__ ol)
{
    int gw   = (blockIdx.x * blockDim.x + threadIdx.x) >> 5;
    int lane = threadIdx.x & 31;
    const float4* xr = (const float4*)(x + (size_t)gw * CDIM);
    const float4* cr = (const float4*)(cat + (size_t)gw * CDIM);
    float4 a0 = xr[lane];
    float4 a1 = xr[lane + 32];
    float4 c0 = cr[lane];
    float4 c1 = cr[lane + 32];
    float4 v0 = make_float4(a0.x+c0.x, a0.y+c0.y, a0.z+c0.z, a0.w+c0.w);
    float4 v1 = make_float4(a1.x+c1.x, a1.y+c1.y, a1.z+c1.z, a1.w+c1.w);
    float4* orow = (float4*)(out + (size_t)gw * CDIM);
    orow[lane]      = v0;
    orow[lane + 32] = v1;
    float s  = v0.x+v0.y+v0.z+v0.w + v1.x+v1.y+v1.z+v1.w;
    float ss = v0.x*v0.x+v0.y*v0.y+v0.z*v0.z+v0.w*v0.w
             + v1.x*v1.x+v1.y*v1.y+v1.z*v1.z+v1.w*v1.w;
    #pragma unroll
    for (int o = 16; o; o >>= 1) {
        s  += __shfl_xor_sync(0xffffffffu, s,  o);
        ss += __shfl_xor_sync(0xffffffffu, ss, o);
    }
    float mean = s * (1.0f/CDIM);
    float var  = ss * (1.0f/CDIM) - mean*mean;
    float inv  = rsqrtf(var + 1e-5f);
    const float4* g4 = (const float4*)g;
    const float4* b4 = (const float4*)b;
    float4 G0 = g4[lane];
    float4 B0 = b4[lane];
    float4 G1 = g4[lane+32];
    float4 B1 = b4[lane+32];
    float4 o0, o1;
    o0.x = (v0.x-mean)*inv*G0.x + B0.x;
    o0.y = (v0.y-mean)*inv*G0.y + B0.y;
    o0.z = (v0.z-mean)*inv*G0.z + B0.z;
    o0.w = (v0.w-mean)*inv*G0.w + B0.w;
    o1.x = (v1.x-mean)*inv*G1.x + B1.x;
    o1.y = (v1.y-mean)*inv*G1.y + B1.y;
    o1.z = (v1.z-mean)*inv*G1.z + B1.z;
    o1.w = (v1.w-mean)*inv*G1.w + B1.w;
    size_t base = (size_t)gw * CDIM + lane * 4;
    split_store4(oh + base,       ol + base,       o0);
    split_store4(oh + base + 128, ol + base + 128, o1);
}

// ---------------- 7x7 mean pooling ----------------
__global__ void pool_kernel(const __nv_bfloat16* __restrict__ xh,
                            const __nv_bfloat16* __restrict__ xl,
                            __nv_bfloat16* __restrict__ ph, __nv_bfloat16* __restrict__ pl)
{
    int t = blockIdx.x * blockDim.x + threadIdx.x;
    int c = t & 255;
    int g = (t >> 8) & 255;
    int b = t >> 16;
    int gy = g >> 4;
    int gx = g & 15;
    float s = 0.0f;
    #pragma unroll
    for (int py = 0; py < WSZ; py++) {
        int rowbase = (gy*WSZ + py) * HW + gx*WSZ;
        #pragma unroll
        for (int px = 0; px < WSZ; px++) {
            size_t idx = ((size_t)b*NTOK + rowbase + px) * CDIM + c;
            s += __bfloat162float(xh[idx]) + __bfloat162float(xl[idx]);
        }
    }
    float v = s * (1.0f/49.0f);
    __nv_bfloat16 h = __float2bfloat16(v);
    ph[t] = h;
    pl[t] = __float2bfloat16(v - __bfloat162float(h));
}

// ---------------- tensor-core bf16x3 GEMM (unchanged from R3) ----------------
__global__ void __launch_bounds__(128, 2) mma_gemm(
    const __nv_bfloat16* __restrict__ Ah, const __nv_bfloat16* __restrict__ Al,
    const __nv_bfloat16* __restrict__ Bh, const __nv_bfloat16* __restrict__ Bl,
    const float* __restrict__ bias, const float* __restrict__ addsrc,
    float* __restrict__ C, int M, int N, int K, int ldc, int coff)
{
    extern __shared__ __nv_bfloat16 sh[];
    int tid  = threadIdx.x;
    int lane = tid & 31;
    int warp = tid >> 5;
    int wm = (warp & 1) * 64;
    int wn = (warp >> 1) * 64;
    int bm = blockIdx.y * 128;
    int bn = blockIdx.x * 128;

    float acc[4][8][4];
    #pragma unroll
    for (int i = 0; i < 4; i++) {
        #pragma unroll
        for (int j = 0; j < 8; j++) {
            #pragma unroll
            for (int e = 0; e < 4; e++) {
                acc[i][j][e] = 0.0f;
            }
        }
    }

    int nIter = K >> 5;

    gemm_stage(sh, tid, Ah, Al, Bh, Bl, bm, bn, K, 0);
    asm volatile("cp.async.commit_group;" ::: "memory");

    for (int it = 0; it < nIter; it++) {
        int st = it & 1;
        if (it + 1 < nIter) {
            gemm_stage(sh + (st^1)*4*TILEB, tid, Ah, Al, Bh, Bl, bm, bn, K, (it+1) << 5);
            asm volatile("cp.async.commit_group;" ::: "memory");
            asm volatile("cp.async.wait_group 1;" ::: "memory");
        } else {
            asm volatile("cp.async.wait_group 0;" ::: "memory");
        }
        __syncthreads();

        const __nv_bfloat16* cA0 = sh + st*4*TILEB;
        const __nv_bfloat16* cA1 = cA0 + TILEB;
        const __nv_bfloat16* cB0 = cA0 + 2*TILEB;
        const __nv_bfloat16* cB1 = cA0 + 3*TILEB;

        #pragma unroll
        for (int kk = 0; kk < 2; kk++) {
            unsigned afh[4][4];
            unsigned afl[4][4];
            #pragma unroll
            for (int mi = 0; mi < 4; mi++) {
                int row = wm + mi*16 + (lane & 15);
                int col = kk*16 + (lane >> 4) * 8;
                ldsm4(afh[mi], smem_u32(cA0 + row*PADK + col));
                ldsm4(afl[mi], smem_u32(cA1 + row*PADK + col));
            }
            #pragma unroll
            for (int np = 0; np < 4; np++) {
                unsigned bfh[4];
                unsigned bfl[4];
                int row = wn + np*16 + (lane >> 4) * 8 + (lane & 7);
                int col = kk*16 + ((lane >> 3) & 1) * 8;
                ldsm4(bfh, smem_u32(cB0 + row*PADK + col));
                ldsm4(bfl, smem_u32(cB1 + row*PADK + col));
                #pragma unroll
                for (int mi = 0; mi < 4; mi++) {
                    mma_bf16(acc[mi][2*np],   afh[mi], &bfh[0]);
                    mma_bf16(acc[mi][2*np+1], afh[mi], &bfh[2]);
                }
                #pragma unroll
                for (int mi = 0; mi < 4; mi++) {
                    mma_bf16(acc[mi][2*np],   afh[mi], &bfl[0]);
                    mma_bf16(acc[mi][2*np+1], afh[mi], &bfl[2]);
                }
                #pragma unroll
                for (int mi = 0; mi < 4; mi++) {
                    mma_bf16(acc[mi][2*np],   afl[mi], &bfh[0]);
                    mma_bf16(acc[mi][2*np+1], afl[mi], &bfh[2]);
                }
            }
        }
        __syncthreads();
    }

    int gg = lane >> 2;
    int t2 = (lane & 3) * 2;
    #pragma unroll
    for (int mi = 0; mi < 4; mi++) {
        #pragma unroll
        for (int half = 0; half < 2; half++) {
            int row = bm + wm + mi*16 + gg + half*8;
            #pragma unroll
            for (int ni = 0; ni < 8; ni++) {
                int col = bn + wn + ni*8 + t2;
                float2 bv = *(const float2*)&bias[col];
                float v0 = acc[mi][ni][half*2 + 0] + bv.x;
                float v1 = acc[mi][ni][half*2 + 1] + bv.y;
                size_t off = (size_t)row * ldc + coff + col;
                if (addsrc) {
                    float2 sv = *(const float2*)&addsrc[off];
                    v0 += sv.x;
                    v1 += sv.y;
                }
                *(float2*)&C[off] = make_float2(v0, v1);
            }
        }
    }
}

// ---------------- global attention (f32x2 packed math) ----------------
__global__ void __launch_bounds__(128) gattn_kernel(
    const float* __restrict__ q, const float* __restrict__ kv,
    __nv_bfloat16* __restrict__ oh, __nv_bfloat16* __restrict__ ol)
{
    __shared__ float ks[128][HD];
    __shared__ float vs[128][HD];
    int bi = blockIdx.x;
    int qc = bi % (NTOK/128);
    int h  = (bi / (NTOK/128)) & (GH-1);
    int b  = bi / ((NTOK/128) * GH);
    int tid = threadIdx.x;
    int n   = qc*128 + tid;
    size_t qrow = (size_t)(b*NTOK + n) * GD + h*HD;

    unsigned long long q2[16];
    {
        const ulonglong2* qp = (const ulonglong2*)&q[qrow];
        #pragma unroll
        for (int j = 0; j < 8; j++) {
            ulonglong2 t = qp[j];
            q2[2*j]   = t.x;
            q2[2*j+1] = t.y;
        }
    }

    float mx = -INFINITY;
    float l = 0.0f;
    unsigned long long a2[16];
    #pragma unroll
    for (int d = 0; d < 16; d++) {
        a2[d] = 0ULL;
    }

    for (int ch = 0; ch < 2; ch++) {
        #pragma unroll
        for (int j = 0; j < 8; j++) {
            int f4 = tid + 128*j;
            int m  = f4 >> 3;
            int d4 = (f4 & 7) * 4;
            size_t kvrow = (size_t)(b*MPOOL + ch*128 + m) * (2*GD) + h*HD;
            *(float4*)&ks[m][d4] = *(const float4*)&kv[kvrow + d4];
            *(float4*)&vs[m][d4] = *(const float4*)&kv[kvrow + GD + d4];
        }
        __syncthreads();
        for (int m = 0; m < 128; m++) {
            const ulonglong2* kp = (const ulonglong2*)ks[m];
            unsigned long long s0 = 0ULL, s1 = 0ULL, s2 = 0ULL, s3 = 0ULL;
            #pragma unroll
            for (int i = 0; i < 4; i++) {
                ulonglong2 ka = kp[2*i];
                ulonglong2 kb = kp[2*i+1];
                fma2(s0, q2[4*i+0], ka.x);
                fma2(s1, q2[4*i+1], ka.y);
                fma2(s2, q2[4*i+2], kb.x);
                fma2(s3, q2[4*i+3], kb.y);
            }
            float2 f0 = unpack2(s0);
            float2 f1 = unpack2(s1);
            float2 f2 = unpack2(s2);
            float2 f3 = unpack2(s3);
            float sdot = (f0.x + f0.y) + (f1.x + f1.y) + (f2.x + f2.y) + (f3.x + f3.y);
            float sc = sdot * ATT_SCALE;
            if (sc > mx) {
                float corr = __expf(mx - sc);
                l *= corr;
                unsigned long long c2 = pack2(corr);
                #pragma unroll
                for (int d = 0; d < 16; d++) {
                    mul2(a2[d], c2);
                }
                mx = sc;
            }
            float p = __expf(sc - mx);
            l += p;
            unsigned long long p2 = pack2(p);
            const ulonglong2* vp = (const ulonglong2*)vs[m];
            #pragma unroll
            for (int i = 0; i < 8; i++) {
                ulonglong2 va = vp[i];
                fma2(a2[2*i],   p2, va.x);
                fma2(a2[2*i+1], p2, va.y);
            }
        }
        __syncthreads();
    }

    float inv = 1.0f / l;
    #pragma unroll
    for (int j = 0; j < 8; j++) {
        float2 u0 = unpack2(a2[2*j]);
        float2 u1 = unpack2(a2[2*j+1]);
        float4 o = make_float4(u0.x*inv, u0.y*inv, u1.x*inv, u1.y*inv);
        split_store4(oh + qrow + 4*j, ol + qrow + 4*j, o);
    }
}

// ---------------- local window attention (f32x2 packed math) ----------------
__global__ void __launch_bounds__(128) lattn_kernel(
    const float* __restrict__ ql, const float* __restrict__ kvl,
    __nv_bfloat16* __restrict__ oh, __nv_bfloat16* __restrict__ ol)
{
    __shared__ float ks[2][49][HD];
    __shared__ float vs[2][49][HD];
    int bi = blockIdx.x;
    int hp = bi & 1;
    int wi = (bi >> 1) & 255;
    int b  = bi >> 9;
    int wy = wi >> 4;
    int wx = wi & 15;
    int tid = threadIdx.x;

    for (int i = tid; i < 2*49*8; i += 128) {
        int d4 = (i & 7) * 4;
        int t  = (i >> 3) % 49;
        int hh = i / (49*8);
        int py = t / WSZ;
        int px = t % WSZ;
        int n  = (wy*WSZ + py)*HW + wx*WSZ + px;
        size_t rowb = (size_t)(b*NTOK + n) * (2*LD) + (hp*2 + hh)*HD;
        *(float4*)&ks[hh][t][d4] = *(const float4*)&kvl[rowb + d4];
        *(float4*)&vs[hh][t][d4] = *(const float4*)&kvl[rowb + LD + d4];
    }
    __syncthreads();

    if (tid < 98) {
        int hh = tid / 49;
        int qi = tid % 49;
        int h  = hp*2 + hh;
        int py = qi / WSZ;
        int px = qi % WSZ;
        int n  = (wy*WSZ + py)*HW + wx*WSZ + px;
        size_t qrow = (size_t)(b*NTOK + n) * LD + h*HD;

        unsigned long long q2[16];
        const ulonglong2* qp = (const ulonglong2*)&ql[qrow];
        #pragma unroll
        for (int j = 0; j < 8; j++) {
            ulonglong2 t = qp[j];
            q2[2*j]   = t.x;
            q2[2*j+1] = t.y;
        }

        float sc[49];
        float mx = -INFINITY;
        #pragma unroll
        for (int t = 0; t < 49; t++) {
            const ulonglong2* kp = (const ulonglong2*)ks[hh][t];
            unsigned long long s0 = 0ULL, s1 = 0ULL, s2 = 0ULL, s3 = 0ULL;
            #pragma unroll
            for (int i = 0; i < 4; i++) {
                ulonglong2 ka = kp[2*i];
                ulonglong2 kb = kp[2*i+1];
                fma2(s0, q2[4*i+0], ka.x);
                fma2(s1, q2[4*i+1], ka.y);
                fma2(s2, q2[4*i+2], kb.x);
                fma2(s3, q2[4*i+3], kb.y);
            }
            float2 f0 = unpack2(s0);
            float2 f1 = unpack2(s1);
            float2 f2 = unpack2(s2);
            float2 f3 = unpack2(s3);
            float s = ((f0.x + f0.y) + (f1.x + f1.y) + (f2.x + f2.y) + (f3.x + f3.y)) * ATT_SCALE;
            sc[t] = s;
            mx = fmaxf(mx, s);
        }
        float l = 0.0f;
        #pragma unroll
        for (int t = 0; t < 49; t++) {
            sc[t] = __expf(sc[t] - mx);
            l += sc[t];
        }
        float inv = 1.0f / l;

        unsigned long long a2[16];
        #pragma unroll
        for (int d = 0; d < 16; d++) {
            a2[d] = 0ULL;
        }
        #pragma unroll
        for (int t = 0; t < 49; t++) {
            unsigned long long p2 = pack2(sc[t] * inv);
            const ulonglong2* vp = (const ulonglong2*)vs[hh][t];
            #pragma unroll
            for (int i = 0; i < 8; i++) {
                ulonglong2 va = vp[i];
                fma2(a2[2*i],   p2, va.x);
                fma2(a2[2*i+1], p2, va.y);
            }
        }
        #pragma unroll
        for (int j = 0; j < 8; j++) {
            float2 u0 = unpack2(a2[2*j]);
            float2 u1 = unpack2(a2[2*j+1]);
            float4 o = make_float4(u0.x, u0.y, u1.x, u1.y);
            split_store4(oh + qrow + 4*j, ol + qrow + 4*j, o);
        }
    }
}

// ---------------- depthwise 3x3 conv + exact GELU, 4-row blocked ------------
__device__ __forceinline__ float gelu_exact(float v)
{
    return 0.5f * v * (1.0f + erff(v * 0.70710678118654752f));
}

__global__ void dwconv_gelu_kernel(const float* __restrict__ h, const float* __restrict__ w,
                                   const float* __restrict__ bias,
                                   __nv_bfloat16* __restrict__ oh, __nv_bfloat16* __restrict__ ol)
{
    int t = blockIdx.x * blockDim.x + threadIdx.x;  // 4*28*112*256 threads
    int c4 = t & 255;
    int rest = t >> 8;
    int xx = rest % HW;
    int tmp = rest / HW;
    int y4 = tmp % (HW/4);
    int bb = tmp / (HW/4);
    int yy0 = y4 * 4;
    int c  = c4 * 4;

    float wv[4][9];
    #pragma unroll
    for (int e = 0; e < 4; e++) {
        #pragma unroll
        for (int k = 0; k < 9; k++) {
            wv[e][k] = w[(c+e)*9 + k];
        }
    }

    float4 bz = *(const float4*)&bias[c];
    float4 acc[4];
    #pragma unroll
    for (int oy = 0; oy < 4; oy++) {
        acc[oy] = bz;
    }

    #pragma unroll
    for (int ry = 0; ry < 6; ry++) {
        int y2 = yy0 - 1 + ry;
        if ((unsigned)y2 >= HW) continue;
        #pragma unroll
        for (int dx = 0; dx < 3; dx++) {
            int x2 = xx + dx - 1;
            if ((unsigned)x2 >= HW) continue;
            float4 v = *(const float4*)&h[((size_t)bb*NTOK + y2*HW + x2) * HID + c];
            #pragma unroll
            for (int oy = 0; oy < 4; oy++) {
                int dy = ry - oy;
                if (dy < 0 || dy > 2) continue;
                int k = dy*3 + dx;
                acc[oy].x = fmaf(v.x, wv[0][k], acc[oy].x);
                acc[oy].y = fmaf(v.y, wv[1][k], acc[oy].y);
                acc[oy].z = fmaf(v.z, wv[2][k], acc[oy].z);
                acc[oy].w = fmaf(v.w, wv[3][k], acc[oy].w);
            }
        }
    }

    #pragma unroll
    for (int oy = 0; oy < 4; oy++) {
        float4 a = acc[oy];
        a.x = gelu_exact(a.x);
        a.y = gelu_exact(a.y);
        a.z = gelu_exact(a.z);
        a.w = gelu_exact(a.w);
        size_t off = ((size_t)bb*NTOK + (yy0+oy)*HW + xx) * HID + c;
        split_store4(oh + off, ol + off, a);
    }
}

// ---------------- launch ----------------
extern "C" void kernel_launch(void* const* d_in, const int* in_sizes, int n_in,
                              void* d_out, int out_size)
{
    const float* x     = (const float*)d_in[0];
    const float* xr    = (const float*)d_in[1];
    const float* g1    = (const float*)d_in[2];
    const float* b1    = (const float*)d_in[3];
    const float* g2    = (const float*)d_in[4];
    const float* b2    = (const float*)d_in[5];
    const float* Gq_w  = (const float*)d_in[6];
    const float* Gq_b  = (const float*)d_in[7];
    const float* Gkv_w = (const float*)d_in[8];
    const float* Gkv_b = (const float*)d_in[9];
    const float* Gp_w  = (const float*)d_in[10];
    const float* Gp_b  = (const float*)d_in[11];
    const float* Lq_w  = (const float*)d_in[12];
    const float* Lq_b  = (const float*)d_in[13];
    const float* Lkv_w = (const float*)d_in[14];
    const float* Lkv_b = (const float*)d_in[15];
    const float* Lp_w  = (const float*)d_in[16];
    const float* Lp_b  = (const float*)d_in[17];
    const float* fc1_w = (const float*)d_in[18];
    const float* fc1_b = (const float*)d_in[19];
    const float* dw_w  = (const float*)d_in[20];
    const float* dw_b  = (const float*)d_in[21];
    const float* fc2_w = (const float*)d_in[22];
    const float* fc2_b = (const float*)d_in[23];
    float* out = (float*)d_out;

    __nv_bfloat16 *p_xn_h;
    __nv_bfloat16 *p_xn_l;
    __nv_bfloat16 *p_xrn_h;
    __nv_bfloat16 *p_xrn_l;
    __nv_bfloat16 *p_pool_h;
    __nv_bfloat16 *p_pool_l;
    __nv_bfloat16 *p_gatt_h;
    __nv_bfloat16 *p_gatt_l;
    __nv_bfloat16 *p_latt_h;
    __nv_bfloat16 *p_latt_l;
    __nv_bfloat16 *p_ln2_h;
    __nv_bfloat16 *p_ln2_l;
    __nv_bfloat16 *p_h2_h;
    __nv_bfloat16 *p_h2_l;
    float *p_q;
    float *p_kv;
    float *p_ql;
    float *p_kvl;
    float *p_cat;
    float *p_h1;
    __nv_bfloat16 *p_wgq_h;
    __nv_bfloat16 *p_wgq_l;
    __nv_bfloat16 *p_wgkv_h;
    __nv_bfloat16 *p_wgkv_l;
    __nv_bfloat16 *p_wgp_h;
    __nv_bfloat16 *p_wgp_l;
    __nv_bfloat16 *p_wlq_h;
    __nv_bfloat16 *p_wlq_l;
    __nv_bfloat16 *p_wlkv_h;
    __nv_bfloat16 *p_wlkv_l;
    __nv_bfloat16 *p_wlp_h;
    __nv_bfloat16 *p_wlp_l;
    __nv_bfloat16 *p_wfc1_h;
    __nv_bfloat16 *p_wfc1_l;
    __nv_bfloat16 *p_wfc2_h;
    __nv_bfloat16 *p_wfc2_l;

    cudaGetSymbolAddress((void**)&p_xn_h, g_xn_h);
    cudaGetSymbolAddress((void**)&p_xn_l, g_xn_l);
    cudaGetSymbolAddress((void**)&p_xrn_h, g_xrn_h);
    cudaGetSymbolAddress((void**)&p_xrn_l, g_xrn_l);
    cudaGetSymbolAddress((void**)&p_pool_h, g_pool_h);
    cudaGetSymbolAddress((void**)&p_pool_l, g_pool_l);
    cudaGetSymbolAddress((void**)&p_gatt_h, g_gatt_h);
    cudaGetSymbolAddress((void**)&p_gatt_l, g_gatt_l);
    cudaGetSymbolAddress((void**)&p_latt_h, g_latt_h);
    cudaGetSymbolAddress((void**)&p_latt_l, g_latt_l);
    cudaGetSymbolAddress((void**)&p_ln2_h, g_ln2_h);
    cudaGetSymbolAddress((void**)&p_ln2_l, g_ln2_l);
    cudaGetSymbolAddress((void**)&p_h2_h, g_h2_h);
    cudaGetSymbolAddress((void**)&p_h2_l, g_h2_l);
    cudaGetSymbolAddress((void**)&p_q, g_q);
    cudaGetSymbolAddress((void**)&p_kv, g_kv);
    cudaGetSymbolAddress((void**)&p_ql, g_ql);
    cudaGetSymbolAddress((void**)&p_kvl, g_kvl);
    cudaGetSymbolAddress((void**)&p_cat, g_cat);
    cudaGetSymbolAddress((void**)&p_h1, g_h1);
    cudaGetSymbolAddress((void**)&p_wgq_h, w_gq_h);
    cudaGetSymbolAddress((void**)&p_wgq_l, w_gq_l);
    cudaGetSymbolAddress((void**)&p_wgkv_h, w_gkv_h);
    cudaGetSymbolAddress((void**)&p_wgkv_l, w_gkv_l);
    cudaGetSymbolAddress((void**)&p_wgp_h, w_gp_h);
    cudaGetSymbolAddress((void**)&p_wgp_l, w_gp_l);
    cudaGetSymbolAddress((void**)&p_wlq_h, w_lq_h);
    cudaGetSymbolAddress((void**)&p_wlq_l, w_lq_l);
    cudaGetSymbolAddress((void**)&p_wlkv_h, w_lkv_h);
    cudaGetSymbolAddress((void**)&p_wlkv_l, w_lkv_l);
    cudaGetSymbolAddress((void**)&p_wlp_h, w_lp_h);
    cudaGetSymbolAddress((void**)&p_wlp_l, w_lp_l);
    cudaGetSymbolAddress((void**)&p_wfc1_h, w_fc1_h);
    cudaGetSymbolAddress((void**)&p_wfc1_l, w_fc1_l);
    cudaGetSymbolAddress((void**)&p_wfc2_h, w_fc2_h);
    cudaGetSymbolAddress((void**)&p_wfc2_l, w_fc2_l);

    const int SMEM = 2 * 4 * TILEB * (int)sizeof(__nv_bfloat16);   // 81920
    cudaFuncSetAttribute(mma_gemm, cudaFuncAttributeMaxDynamicSharedMemorySize, SMEM);

    // 1. weight transpose + split (single launch)
    wtrans_all<<<2944, 256>>>(Gq_w, Gkv_w, Gp_w, Lq_w, Lkv_w, Lp_w, fc1_w, fc2_w);

    // 2-3. LayerNorms
    ln_kernel<<<ROWS/8, 256>>>(x,  g1, b1, p_xn_h,  p_xn_l,  ROWS);
    ln_kernel<<<ROWS/8, 256>>>(xr, g1, b1, p_xrn_h, p_xrn_l, ROWS);

    // 4. Pool
    pool_kernel<<<(BATCH*MPOOL*CDIM)/256, 256>>>(p_xrn_h, p_xrn_l, p_pool_h, p_pool_l);

    // 5. Gkv projection (small), 6. Gq projection (ncu -s 5 captures this one)
    mma_gemm<<<dim3(2, (BATCH*MPOOL)/128), 128, SMEM>>>(p_pool_h, p_pool_l, p_wgkv_h, p_wgkv_l, Gkv_b, 0,
                                               p_kv, BATCH*MPOOL, 2*GD, CDIM, 2*GD, 0);
    mma_gemm<<<dim3(1, ROWS/128), 128, SMEM>>>(p_xn_h, p_xn_l, p_wgq_h, p_wgq_l, Gq_b, 0,
                                               p_q, ROWS, GD, CDIM, GD, 0);
    // 7-8. Lq / Lkv projections
    mma_gemm<<<dim3(1, ROWS/128), 128, SMEM>>>(p_xn_h, p_xn_l, p_wlq_h, p_wlq_l, Lq_b, 0,
                                               p_ql, ROWS, LD, CDIM, LD, 0);
    mma_gemm<<<dim3(2, ROWS/128), 128, SMEM>>>(p_xrn_h, p_xrn_l, p_wlkv_h, p_wlkv_l, Lkv_b, 0,
                                               p_kvl, ROWS, 2*LD, CDIM, 2*LD, 0);

    // 9-10. Attentions
    gattn_kernel<<<BATCH*GH*(NTOK/128), 128>>>(p_q, p_kv, p_gatt_h, p_gatt_l);
    lattn_kernel<<<BATCH*256*2, 128>>>(p_ql, p_kvl, p_latt_h, p_latt_l);

    // 11-12. Output projections into concat buffer
    mma_gemm<<<dim3(1, ROWS/128), 128, SMEM>>>(p_gatt_h, p_gatt_l, p_wgp_h, p_wgp_l, Gp_b, 0,
                                               p_cat, ROWS, GD, GD, CDIM, 0);
    mma_gemm<<<dim3(1, ROWS/128), 128, SMEM>>>(p_latt_h, p_latt_l, p_wlp_h, p_wlp_l, Lp_b, 0,
                                               p_cat, ROWS, LD, LD, CDIM, GD);

    // 13. Fused residual add + ln2: out = x + cat; ln2 = LN(out)
    addln_kernel<<<ROWS/8, 256>>>(x, p_cat, g2, b2, out, p_ln2_h, p_ln2_l);

    // 14. FC1
    mma_gemm<<<dim3(8, ROWS/128), 128, SMEM>>>(p_ln2_h, p_ln2_l, p_wfc1_h, p_wfc1_l, fc1_b, 0,
                                               p_h1, ROWS, HID, CDIM, HID, 0);
    // 15. depthwise conv + GELU (4-row blocked)
    dwconv_gelu_kernel<<<(BATCH*(HW/4)*HW*256)/256, 256>>>(p_h1, dw_w, dw_b, p_h2_h, p_h2_l);
    // 16. FC2 + residual
    mma_gemm<<<dim3(2, ROWS/128), 128, SMEM>>>(p_h2_h, p_h2_l, p_wfc2_h, p_wfc2_l, fc2_b, out,
                                               out, ROWS, CDIM, HID, CDIM, 0);
}